// round 2
// baseline (speedup 1.0000x reference)
#include <cuda_runtime.h>

#define T_LEN 16384
#define DIM   1024
#define NCHUNK 256
#define CLEN   64   // T_LEN / NCHUNK

// ---------------- scratch (static device globals; no allocation) ----------------
__device__ __align__(16) float  g_gain[DIM];
__device__ float2 g_lam[DIM];
__device__ float2 g_lamL[DIM];
__device__ float2 g_carry[NCHUNK * DIM];
__device__ __align__(16) float g_bu_re[(size_t)T_LEN * DIM];  // Bu, then hidden (in-place)
__device__ __align__(16) float g_bu_im[(size_t)T_LEN * DIM];

// ---------------- setup: lambda, lambda^CLEN, gamma gain ----------------
__global__ void setup_kernel(const float* __restrict__ nu_log,
                             const float* __restrict__ theta_log,
                             const float* __restrict__ gamma_log) {
    int h = blockIdx.x * blockDim.x + threadIdx.x;
    if (h >= DIM) return;
    float nu = expf(nu_log[h]);
    float th = expf(theta_log[h]);
    float r  = expf(-nu);
    float lr = r * cosf(th);
    float li = r * sinf(th);
    g_lam[h] = make_float2(lr, li);
    // lambda^64 via 6 squarings
    float ar = lr, ai = li;
#pragma unroll
    for (int s = 0; s < 6; s++) {
        float nr = ar * ar - ai * ai;
        float ni = 2.0f * ar * ai;
        ar = nr; ai = ni;
    }
    g_lamL[h] = make_float2(ar, ai);
    g_gain[h] = expf(gamma_log[h]);
}

// ---------------- GEMM1: Bu = (X * g) @ (B_re, B_im) ----------------
// BM=128, BN=64, BK=16, 256 threads, 8x4 micro-tile, dual accumulator
__global__ __launch_bounds__(256) void gemm_bu(const float* __restrict__ X,
                                               const float* __restrict__ Bre,
                                               const float* __restrict__ Bim) {
    __shared__ float As [16][132];
    __shared__ float Brs[16][68];
    __shared__ float Bis[16][68];

    int tid = threadIdx.x;
    int tx = tid & 15;   // n direction (16 lanes * 4 = 64)
    int ty = tid >> 4;   // m direction (16 lanes * 8 = 128)
    int n0 = blockIdx.x * 64;
    int m0 = blockIdx.y * 128;

    float accr[8][4];
    float acci[8][4];
#pragma unroll
    for (int r = 0; r < 8; r++)
#pragma unroll
        for (int c = 0; c < 4; c++) { accr[r][c] = 0.f; acci[r][c] = 0.f; }

    int arow0 = tid >> 2;          // 0..63 (second half +64)
    int akg   = (tid & 3) * 4;     // k offset within tile
    int brow  = tid >> 4;          // 0..15 (k)
    int bcg   = (tid & 15) * 4;    // n offset

    for (int k0 = 0; k0 < DIM; k0 += 16) {
        // A tile (scaled by gain on the K index), stored transposed As[k][m]
#pragma unroll
        for (int s = 0; s < 2; s++) {
            int row = arow0 + s * 64;
            float4 v = *(const float4*)(X + (size_t)(m0 + row) * DIM + k0 + akg);
            float4 g = *(const float4*)(&g_gain[k0 + akg]);
            As[akg + 0][row] = v.x * g.x;
            As[akg + 1][row] = v.y * g.y;
            As[akg + 2][row] = v.z * g.z;
            As[akg + 3][row] = v.w * g.w;
        }
        // B tiles, direct [k][n]
        *(float4*)(&Brs[brow][bcg]) = *(const float4*)(Bre + (size_t)(k0 + brow) * DIM + n0 + bcg);
        *(float4*)(&Bis[brow][bcg]) = *(const float4*)(Bim + (size_t)(k0 + brow) * DIM + n0 + bcg);
        __syncthreads();

#pragma unroll
        for (int kk = 0; kk < 16; kk++) {
            float4 a0 = *(const float4*)(&As[kk][ty * 8]);
            float4 a1 = *(const float4*)(&As[kk][ty * 8 + 4]);
            float a[8] = {a0.x, a0.y, a0.z, a0.w, a1.x, a1.y, a1.z, a1.w};
            float4 b4r = *(const float4*)(&Brs[kk][tx * 4]);
            float4 b4i = *(const float4*)(&Bis[kk][tx * 4]);
            float br_[4] = {b4r.x, b4r.y, b4r.z, b4r.w};
            float bi_[4] = {b4i.x, b4i.y, b4i.z, b4i.w};
#pragma unroll
            for (int r = 0; r < 8; r++)
#pragma unroll
                for (int c = 0; c < 4; c++) {
                    accr[r][c] = fmaf(a[r], br_[c], accr[r][c]);
                    acci[r][c] = fmaf(a[r], bi_[c], acci[r][c]);
                }
        }
        __syncthreads();
    }

#pragma unroll
    for (int r = 0; r < 8; r++) {
        size_t o = (size_t)(m0 + ty * 8 + r) * DIM + n0 + tx * 4;
        *(float4*)(&g_bu_re[o]) = make_float4(accr[r][0], accr[r][1], accr[r][2], accr[r][3]);
        *(float4*)(&g_bu_im[o]) = make_float4(acci[r][0], acci[r][1], acci[r][2], acci[r][3]);
    }
}

// ---------------- scan pass 1: chunk-local scan (in place), record chunk ends ----------------
__global__ __launch_bounds__(256) void scan_local() {
    int h = blockIdx.y * blockDim.x + threadIdx.x;
    int c = blockIdx.x;
    float2 lam = g_lam[h];
    float ar = 0.f, ai = 0.f;
    size_t idx = (size_t)c * CLEN * DIM + h;
#pragma unroll 4
    for (int t = 0; t < CLEN; t++, idx += DIM) {
        float br = g_bu_re[idx];
        float bi = g_bu_im[idx];
        float nr = fmaf(lam.x, ar, fmaf(-lam.y, ai, br));
        float ni = fmaf(lam.x, ai, fmaf( lam.y, ar, bi));
        ar = nr; ai = ni;
        g_bu_re[idx] = ar;
        g_bu_im[idx] = ai;
    }
    g_carry[c * DIM + h] = make_float2(ar, ai);
}

// ---------------- scan pass 2: prefix over chunk carries (per channel) ----------------
__global__ __launch_bounds__(256) void scan_chunks() {
    int h = blockIdx.x * blockDim.x + threadIdx.x;
    float2 lamL = g_lamL[h];
    float pr = 0.f, pi = 0.f;
    for (int c = 0; c < NCHUNK; c++) {
        float2 e = g_carry[c * DIM + h];
        float nr = fmaf(lamL.x, pr, fmaf(-lamL.y, pi, e.x));
        float ni = fmaf(lamL.x, pi, fmaf( lamL.y, pr, e.y));
        pr = nr; pi = ni;
        g_carry[c * DIM + h] = make_float2(pr, pi);   // inclusive prefix P_c
    }
}

// ---------------- scan pass 3: broadcast carry into chunks 1..NCHUNK-1 ----------------
__global__ __launch_bounds__(256) void scan_apply() {
    int h = blockIdx.y * blockDim.x + threadIdx.x;
    int c = blockIdx.x + 1;                       // chunks 1..255
    float2 P = g_carry[(c - 1) * DIM + h];        // carry-in = prefix of previous chunk
    float2 lam = g_lam[h];
    float fr = lam.x, fi = lam.y;                 // lambda^(t-offset+1)
    size_t idx = (size_t)c * CLEN * DIM + h;
#pragma unroll 4
    for (int t = 0; t < CLEN; t++, idx += DIM) {
        g_bu_re[idx] = fmaf(fr, P.x, fmaf(-fi, P.y, g_bu_re[idx]));
        g_bu_im[idx] = fmaf(fr, P.y, fmaf( fi, P.x, g_bu_im[idx]));
        float nfr = fr * lam.x - fi * lam.y;
        float nfi = fr * lam.y + fi * lam.x;
        fr = nfr; fi = nfi;
    }
}

// ---------------- GEMM2: out = Hr@Cre^T - Hi@Cim^T + X@D ----------------
// BM=128, BN=128, BK=8, 256 threads, 8x8 micro-tile, triple product fused
__global__ __launch_bounds__(256) void gemm_out(const float* __restrict__ X,
                                                const float* __restrict__ Cre,
                                                const float* __restrict__ Cim,
                                                const float* __restrict__ Dm,
                                                float* __restrict__ out) {
    __shared__ float Ahr[8][132];
    __shared__ float Ahi[8][132];
    __shared__ float Ax [8][132];
    __shared__ float Bcr[8][132];
    __shared__ float Bci[8][132];
    __shared__ float Bd [8][132];

    int tid = threadIdx.x;
    int tx = tid & 15;   // n direction (16 * 8 = 128)
    int ty = tid >> 4;   // m direction (16 * 8 = 128)
    int n0 = blockIdx.x * 128;
    int m0 = blockIdx.y * 128;

    float acc[8][8];
#pragma unroll
    for (int r = 0; r < 8; r++)
#pragma unroll
        for (int c = 0; c < 8; c++) acc[r][c] = 0.f;

    int arow = tid >> 1;          // 0..127
    int akg  = (tid & 1) * 4;     // 0 or 4
    int dr   = tid >> 5;          // 0..7
    int dcg  = (tid & 31) * 4;    // 0..124

    for (int k0 = 0; k0 < DIM; k0 += 8) {
        {   // A tiles (Hr, Hi, X), transposed [k][m]
            size_t gi = (size_t)(m0 + arow) * DIM + k0 + akg;
            float4 vr = *(const float4*)(g_bu_re + gi);
            float4 vi = *(const float4*)(g_bu_im + gi);
            float4 vx = *(const float4*)(X + gi);
            Ahr[akg + 0][arow] = vr.x; Ahr[akg + 1][arow] = vr.y;
            Ahr[akg + 2][arow] = vr.z; Ahr[akg + 3][arow] = vr.w;
            Ahi[akg + 0][arow] = vi.x; Ahi[akg + 1][arow] = vi.y;
            Ahi[akg + 2][arow] = vi.z; Ahi[akg + 3][arow] = vi.w;
            Ax [akg + 0][arow] = vx.x; Ax [akg + 1][arow] = vx.y;
            Ax [akg + 2][arow] = vx.z; Ax [akg + 3][arow] = vx.w;
        }
        {   // C tiles: C[o,k] -> Bs[k][n] (transposed load)
            size_t gi = (size_t)(n0 + arow) * DIM + k0 + akg;
            float4 vr = *(const float4*)(Cre + gi);
            float4 vi = *(const float4*)(Cim + gi);
            Bcr[akg + 0][arow] = vr.x; Bcr[akg + 1][arow] = vr.y;
            Bcr[akg + 2][arow] = vr.z; Bcr[akg + 3][arow] = vr.w;
            Bci[akg + 0][arow] = vi.x; Bci[akg + 1][arow] = vi.y;
            Bci[akg + 2][arow] = vi.z; Bci[akg + 3][arow] = vi.w;
        }
        // D tile: D[k,n] direct
        *(float4*)(&Bd[dr][dcg]) = *(const float4*)(Dm + (size_t)(k0 + dr) * DIM + n0 + dcg);
        __syncthreads();

#pragma unroll
        for (int kk = 0; kk < 8; kk++) {
            float4 h0 = *(const float4*)(&Ahr[kk][ty * 8]);
            float4 h1 = *(const float4*)(&Ahr[kk][ty * 8 + 4]);
            float4 i0 = *(const float4*)(&Ahi[kk][ty * 8]);
            float4 i1 = *(const float4*)(&Ahi[kk][ty * 8 + 4]);
            float4 x0 = *(const float4*)(&Ax [kk][ty * 8]);
            float4 x1 = *(const float4*)(&Ax [kk][ty * 8 + 4]);
            float ahr[8] = {h0.x, h0.y, h0.z, h0.w, h1.x, h1.y, h1.z, h1.w};
            float ahi[8] = {i0.x, i0.y, i0.z, i0.w, i1.x, i1.y, i1.z, i1.w};
            float ax [8] = {x0.x, x0.y, x0.z, x0.w, x1.x, x1.y, x1.z, x1.w};

            float4 c0 = *(const float4*)(&Bcr[kk][tx * 8]);
            float4 c1 = *(const float4*)(&Bcr[kk][tx * 8 + 4]);
            float4 s0 = *(const float4*)(&Bci[kk][tx * 8]);
            float4 s1 = *(const float4*)(&Bci[kk][tx * 8 + 4]);
            float4 d0 = *(const float4*)(&Bd [kk][tx * 8]);
            float4 d1 = *(const float4*)(&Bd [kk][tx * 8 + 4]);
            float bcr[8] = {c0.x, c0.y, c0.z, c0.w, c1.x, c1.y, c1.z, c1.w};
            float bci[8] = {s0.x, s0.y, s0.z, s0.w, s1.x, s1.y, s1.z, s1.w};
            float bd [8] = {d0.x, d0.y, d0.z, d0.w, d1.x, d1.y, d1.z, d1.w};

#pragma unroll
            for (int r = 0; r < 8; r++)
#pragma unroll
                for (int c = 0; c < 8; c++) {
                    float v = acc[r][c];
                    v = fmaf(ahr[r],  bcr[c], v);
                    v = fmaf(-ahi[r], bci[c], v);
                    v = fmaf(ax[r],   bd[c],  v);
                    acc[r][c] = v;
                }
        }
        __syncthreads();
    }

#pragma unroll
    for (int r = 0; r < 8; r++) {
        size_t o = (size_t)(m0 + ty * 8 + r) * DIM + n0 + tx * 8;
        *(float4*)(&out[o])     = make_float4(acc[r][0], acc[r][1], acc[r][2], acc[r][3]);
        *(float4*)(&out[o + 4]) = make_float4(acc[r][4], acc[r][5], acc[r][6], acc[r][7]);
    }
}

// ---------------- launch ----------------
extern "C" void kernel_launch(void* const* d_in, const int* in_sizes, int n_in,
                              void* d_out, int out_size) {
    const float* X         = (const float*)d_in[0];
    const float* nu_log    = (const float*)d_in[1];
    const float* theta_log = (const float*)d_in[2];
    const float* gamma_log = (const float*)d_in[3];
    const float* Bre       = (const float*)d_in[4];
    const float* Bim       = (const float*)d_in[5];
    const float* Cre       = (const float*)d_in[6];
    const float* Cim       = (const float*)d_in[7];
    const float* Dm        = (const float*)d_in[8];
    float* out             = (float*)d_out;

    setup_kernel<<<4, 256>>>(nu_log, theta_log, gamma_log);
    gemm_bu<<<dim3(DIM / 64, T_LEN / 128), 256>>>(X, Bre, Bim);
    scan_local<<<dim3(NCHUNK, DIM / 256), 256>>>();
    scan_chunks<<<DIM / 256, 256>>>();
    scan_apply<<<dim3(NCHUNK - 1, DIM / 256), 256>>>();
    gemm_out<<<dim3(DIM / 128, T_LEN / 128), 256>>>(X, Cre, Cim, Dm, out);
}